// round 2
// baseline (speedup 1.0000x reference)
#include <cuda_runtime.h>
#include <cuda_bf16.h>

// Problem constants (fixed by the dataset instance)
//   b=4, n1=16384/batch (65536 total), n2=4096/batch (16384 total)
//   Cin1=64, Cin2=128, Cout=64, K=3 neighbors
#define N1TOT 65536
#define N2TOT 16384
#define N1PB  16384
#define N2PB  4096
#define CV    192   // Cout*3

// Scratch: y2 in point-major layout [n][c*3+v] (768 B per point, gather friendly)
__device__ float g_y2t[N2TOT * CV];

// ---------------------------------------------------------------------------
// VN linear + leaky-relu.  x: [CIN][3][N], wf/wd: [64][CIN].
// Block: 32 points, 256 threads = 8 o-groups x 32 point-lanes.
// Each thread accumulates p,d (3-vectors) for 8 output channels of 1 point.
// POINT_MAJOR=false -> write out[(o*3+v)*N + n]   (y1, straight to d_out)
// POINT_MAJOR=true  -> write g_y2t[n*192 + o*3+v] (y2, via smem transpose)
// ---------------------------------------------------------------------------
template <int CIN, bool POINT_MAJOR>
__global__ void __launch_bounds__(256) vn_kernel(
    const float* __restrict__ x, const float* __restrict__ wf,
    const float* __restrict__ wd, float* __restrict__ out, int N)
{
    extern __shared__ float sm[];
    float2* ws = (float2*)sm;                 // [64*CIN] interleaved (wf, wd)
    float*  xs = sm + 2 * 64 * CIN;           // [CIN][3][32]
    const int tid = threadIdx.x;

    for (int i = tid; i < 64 * CIN; i += 256)
        ws[i] = make_float2(wf[i], wd[i]);

    const int n0 = blockIdx.x * 32;
    for (int i = tid; i < CIN * 96; i += 256) {
        int c = i / 96, r = i - c * 96;
        xs[i] = x[(size_t)c * 3 * N + (size_t)(r >> 5) * N + (n0 + (r & 31))];
    }
    __syncthreads();

    const int p  = tid & 31;
    const int og = tid >> 5;

    float aP[8][3], aD[8][3];
#pragma unroll
    for (int i = 0; i < 8; i++)
#pragma unroll
        for (int v = 0; v < 3; v++) { aP[i][v] = 0.f; aD[i][v] = 0.f; }

    for (int c = 0; c < CIN; c++) {
        float xv0 = xs[c * 96 + p];
        float xv1 = xs[c * 96 + 32 + p];
        float xv2 = xs[c * 96 + 64 + p];
#pragma unroll
        for (int i = 0; i < 8; i++) {
            float2 w = ws[(og * 8 + i) * CIN + c];
            aP[i][0] = fmaf(w.x, xv0, aP[i][0]);
            aP[i][1] = fmaf(w.x, xv1, aP[i][1]);
            aP[i][2] = fmaf(w.x, xv2, aP[i][2]);
            aD[i][0] = fmaf(w.y, xv0, aD[i][0]);
            aD[i][1] = fmaf(w.y, xv1, aD[i][1]);
            aD[i][2] = fmaf(w.y, xv2, aD[i][2]);
        }
    }

    // nonlinearity:  dot>=0 -> p ;  dot<0 -> p - 0.8*(dot/(|d|^2+1e-6))*d
    float val[8][3];
#pragma unroll
    for (int i = 0; i < 8; i++) {
        float dot = aP[i][0] * aD[i][0] + aP[i][1] * aD[i][1] + aP[i][2] * aD[i][2];
        float dd  = aD[i][0] * aD[i][0] + aD[i][1] * aD[i][1] + aD[i][2] * aD[i][2];
        float coef = (dot < 0.f) ? (0.8f * dot / (dd + 1e-6f)) : 0.f;
        val[i][0] = aP[i][0] - coef * aD[i][0];
        val[i][1] = aP[i][1] - coef * aD[i][1];
        val[i][2] = aP[i][2] - coef * aD[i][2];
    }

    if (!POINT_MAJOR) {
#pragma unroll
        for (int i = 0; i < 8; i++) {
            int o = og * 8 + i;
#pragma unroll
            for (int v = 0; v < 3; v++)
                out[(size_t)(o * 3 + v) * N + (n0 + p)] = val[i][v];
        }
    } else {
        __syncthreads();                  // done reading xs; reuse as transpose buf
        float* tb = xs;                   // [32][193] (pad -> conflict free)
#pragma unroll
        for (int i = 0; i < 8; i++) {
            int o = og * 8 + i;
#pragma unroll
            for (int v = 0; v < 3; v++)
                tb[p * 193 + (o * 3 + v)] = val[i][v];
        }
        __syncthreads();
        for (int i = tid; i < 32 * CV; i += 256) {
            int pp = i / CV, cv = i - pp * CV;
            g_y2t[(size_t)(n0 + pp) * CV + cv] = tb[pp * 193 + cv];
        }
    }
}

// ---------------------------------------------------------------------------
// Brute-force 3-NN + inverse-sq-dist interpolation + add into out.
// Grid: (N1PB/256, 4 batches). Block caches all 4096 coarse points (float4).
// EXACT fp32 top-3: branchless sorted insertion keeping (d2, idx) registers.
// Strict < preserves lower-index-first on ties, matching lax.top_k.
// ---------------------------------------------------------------------------
__global__ void __launch_bounds__(256) knn_interp_kernel(
    const float* __restrict__ p1, const float* __restrict__ p2,
    float* __restrict__ out)
{
    extern __shared__ float4 s[];              // [4096]
    const int batch = blockIdx.y;
    const float* p2b = p2 + (size_t)batch * N2PB * 3;
    for (int j = threadIdx.x; j < N2PB; j += 256)
        s[j] = make_float4(p2b[3 * j], p2b[3 * j + 1], p2b[3 * j + 2], 0.f);
    __syncthreads();

    const int ng = batch * N1PB + blockIdx.x * 256 + threadIdx.x;
    const float qx = p1[3 * ng], qy = p1[3 * ng + 1], qz = p1[3 * ng + 2];

    float a0 = 3.4e38f, a1 = 3.4e38f, a2 = 3.4e38f;
    int   i0 = 0, i1 = 0, i2 = 0;
#pragma unroll 8
    for (int j = 0; j < N2PB; j++) {
        float4 sp = s[j];
        float dx = qx - sp.x, dy = qy - sp.y, dz = qz - sp.z;
        float d2 = fmaf(dx, dx, fmaf(dy, dy, dz * dz));
        bool c0 = d2 < a0, c1 = d2 < a1, c2 = d2 < a2;
        a2 = c1 ? a1 : (c2 ? d2 : a2);  i2 = c1 ? i1 : (c2 ? j : i2);
        a1 = c0 ? a0 : (c1 ? d2 : a1);  i1 = c0 ? i0 : (c1 ? j : i1);
        a0 = c0 ? d2 : a0;              i0 = c0 ? j : i0;
    }

    float w0 = 1.f / (a0 + 1e-8f);
    float w1 = 1.f / (a1 + 1e-8f);
    float w2 = 1.f / (a2 + 1e-8f);
    float inv = 1.f / (w0 + w1 + w2);
    w0 *= inv; w1 *= inv; w2 *= inv;

    const float4* f0 = (const float4*)(g_y2t + (size_t)(batch * N2PB + i0) * CV);
    const float4* f1 = (const float4*)(g_y2t + (size_t)(batch * N2PB + i1) * CV);
    const float4* f2 = (const float4*)(g_y2t + (size_t)(batch * N2PB + i2) * CV);
    float* op = out + ng;

#pragma unroll 4
    for (int c4 = 0; c4 < CV / 4; c4++) {
        float4 a = f0[c4], b = f1[c4], c = f2[c4];
        op[(size_t)(4 * c4 + 0) * N1TOT] += w0 * a.x + w1 * b.x + w2 * c.x;
        op[(size_t)(4 * c4 + 1) * N1TOT] += w0 * a.y + w1 * b.y + w2 * c.y;
        op[(size_t)(4 * c4 + 2) * N1TOT] += w0 * a.z + w1 * b.z + w2 * c.z;
        op[(size_t)(4 * c4 + 3) * N1TOT] += w0 * a.w + w1 * b.w + w2 * c.w;
    }
}

// ---------------------------------------------------------------------------
extern "C" void kernel_launch(void* const* d_in, const int* in_sizes, int n_in,
                              void* d_out, int out_size)
{
    const float* p1  = (const float*)d_in[0];
    const float* x1  = (const float*)d_in[1];
    const float* p2  = (const float*)d_in[3];
    const float* x2  = (const float*)d_in[4];
    const float* w1f = (const float*)d_in[6];
    const float* w1d = (const float*)d_in[7];
    const float* w2f = (const float*)d_in[8];
    const float* w2d = (const float*)d_in[9];
    float* out = (float*)d_out;

    const int S1 = (2 * 64 * 64  + 64  * 96) * 4;   // 57344  B
    const int S2 = (2 * 64 * 128 + 128 * 96) * 4;   // 114688 B
    const int S3 = N2PB * 16;                       // 65536  B

    cudaFuncSetAttribute((const void*)vn_kernel<64, false>,
                         cudaFuncAttributeMaxDynamicSharedMemorySize, S1);
    cudaFuncSetAttribute((const void*)vn_kernel<128, true>,
                         cudaFuncAttributeMaxDynamicSharedMemorySize, S2);
    cudaFuncSetAttribute((const void*)knn_interp_kernel,
                         cudaFuncAttributeMaxDynamicSharedMemorySize, S3);

    // y1 = VN(x1) -> out (base term)
    vn_kernel<64, false><<<N1TOT / 32, 256, S1>>>(x1, w1f, w1d, out, N1TOT);
    // y2 = VN(x2) -> g_y2t (point-major)
    vn_kernel<128, true><<<N2TOT / 32, 256, S2>>>(x2, w2f, w2d, nullptr, N2TOT);
    // out += knn-interp(y2)
    knn_interp_kernel<<<dim3(N1PB / 256, 4), 256, S3>>>(p1, p2, out);
}

// round 4
// speedup vs baseline: 1.2289x; 1.2289x over previous
#include <cuda_runtime.h>
#include <cuda_bf16.h>

// Problem constants (fixed by the dataset instance)
//   b=4, n1=16384/batch (65536 total), n2=4096/batch (16384 total)
//   Cin1=64, Cin2=128, Cout=64, K=3 neighbors
#define N1TOT 65536
#define N2TOT 16384
#define N1PB  16384
#define N2PB  4096
#define CV    192   // Cout*3

// Scratch: y2 in point-major layout [n][c*3+v] (768 B per point, gather friendly)
__device__ float g_y2t[N2TOT * CV];

// ---------------------------------------------------------------------------
// VN linear + leaky-relu.  x: [CIN][3][N], wf/wd: [64][CIN].
// Block: 32 points, 256 threads = 8 o-groups x 32 point-lanes.
// CIN processed in chunks of 32 staged through 33 KB of smem:
//   ws chunk: [32][66 pad] float2 (wf,wd) pairs, channel-major -> float4 loads
//   xs chunk: [32][32] float4 (x0,x1,x2,-)   -> one LDS.128 per c per thread
// Inner loop per c: 1 LDS.128 (x) + 4 LDS.128 (w) + 48 FFMA  (~90% FFMA mix).
// ---------------------------------------------------------------------------
#define WS_STRIDE 66   // float2 stride per channel row (pad, float4-aligned)

template <int CIN, bool POINT_MAJOR>
__global__ void __launch_bounds__(256, 3) vn_kernel(
    const float* __restrict__ x, const float* __restrict__ wf,
    const float* __restrict__ wd, float* __restrict__ out, int N)
{
    extern __shared__ float sm[];
    float2* ws = (float2*)sm;                        // 32*66 float2 = 16896 B
    float4* xs = (float4*)(sm + 2 * 32 * WS_STRIDE); // 32*32 float4 = 16384 B
    float*  xsf = (float*)xs;
    const int tid = threadIdx.x;
    const int p  = tid & 31;
    const int og = tid >> 5;
    const int n0 = blockIdx.x * 32;

    float aP[8][3], aD[8][3];
#pragma unroll
    for (int i = 0; i < 8; i++)
#pragma unroll
        for (int v = 0; v < 3; v++) { aP[i][v] = 0.f; aD[i][v] = 0.f; }

    for (int c0 = 0; c0 < CIN; c0 += 32) {
        __syncthreads();   // previous chunk fully consumed
        // stage weights: i -> (o = i>>5, cc = i&31); global read coalesced over cc
        for (int i = tid; i < 2048; i += 256) {
            int o = i >> 5, cc = i & 31;
            ws[cc * WS_STRIDE + o] =
                make_float2(wf[o * CIN + c0 + cc], wd[o * CIN + c0 + cc]);
        }
        // stage x: i -> (v = i>>10, cc = (i>>5)&31, pp = i&31); coalesced over pp
        for (int i = tid; i < 3072; i += 256) {
            int v = i >> 10, cc = (i >> 5) & 31, pp = i & 31;
            xsf[(cc * 32 + pp) * 4 + v] =
                x[(size_t)(c0 + cc) * 3 * N + (size_t)v * N + (n0 + pp)];
        }
        __syncthreads();

        const float4* wsv = (const float4*)ws;
#pragma unroll 4
        for (int cc = 0; cc < 32; cc++) {
            float4 xv = xs[cc * 32 + p];
#pragma unroll
            for (int k = 0; k < 4; k++) {
                // (wf[2k], wd[2k], wf[2k+1], wd[2k+1]) for this channel cc
                float4 w2 = wsv[cc * (WS_STRIDE / 2) + og * 4 + k];
                int i = 2 * k;
                aP[i][0] = fmaf(w2.x, xv.x, aP[i][0]);
                aP[i][1] = fmaf(w2.x, xv.y, aP[i][1]);
                aP[i][2] = fmaf(w2.x, xv.z, aP[i][2]);
                aD[i][0] = fmaf(w2.y, xv.x, aD[i][0]);
                aD[i][1] = fmaf(w2.y, xv.y, aD[i][1]);
                aD[i][2] = fmaf(w2.y, xv.z, aD[i][2]);
                aP[i+1][0] = fmaf(w2.z, xv.x, aP[i+1][0]);
                aP[i+1][1] = fmaf(w2.z, xv.y, aP[i+1][1]);
                aP[i+1][2] = fmaf(w2.z, xv.z, aP[i+1][2]);
                aD[i+1][0] = fmaf(w2.w, xv.x, aD[i+1][0]);
                aD[i+1][1] = fmaf(w2.w, xv.y, aD[i+1][1]);
                aD[i+1][2] = fmaf(w2.w, xv.z, aD[i+1][2]);
            }
        }
    }

    // nonlinearity:  dot>=0 -> p ;  dot<0 -> p - 0.8*(dot/(|d|^2+1e-6))*d
    float val[8][3];
#pragma unroll
    for (int i = 0; i < 8; i++) {
        float dot = aP[i][0] * aD[i][0] + aP[i][1] * aD[i][1] + aP[i][2] * aD[i][2];
        float dd  = aD[i][0] * aD[i][0] + aD[i][1] * aD[i][1] + aD[i][2] * aD[i][2];
        float coef = (dot < 0.f) ? (0.8f * dot / (dd + 1e-6f)) : 0.f;
        val[i][0] = aP[i][0] - coef * aD[i][0];
        val[i][1] = aP[i][1] - coef * aD[i][1];
        val[i][2] = aP[i][2] - coef * aD[i][2];
    }

    if (!POINT_MAJOR) {
#pragma unroll
        for (int i = 0; i < 8; i++) {
            int o = og * 8 + i;
#pragma unroll
            for (int v = 0; v < 3; v++)
                out[(size_t)(o * 3 + v) * N + (n0 + p)] = val[i][v];
        }
    } else {
        __syncthreads();                  // done with ws/xs; reuse as transpose buf
        float* tb = sm;                   // [32][193] (pad -> conflict free)
#pragma unroll
        for (int i = 0; i < 8; i++) {
            int o = og * 8 + i;
#pragma unroll
            for (int v = 0; v < 3; v++)
                tb[p * 193 + (o * 3 + v)] = val[i][v];
        }
        __syncthreads();
        for (int i = tid; i < 32 * CV; i += 256) {
            int pp = i / CV, cv = i - pp * CV;
            g_y2t[(size_t)(n0 + pp) * CV + cv] = tb[pp * 193 + cv];
        }
    }
}

// ---------------------------------------------------------------------------
// Brute-force 3-NN + inverse-sq-dist interpolation + add into out.
// Grid: (N1PB/256, 4 batches). Block caches all 4096 coarse points (float4).
// EXACT fp32 top-3: guarded sorted insertion. Fast path per 4 candidates:
// 4 dists + fmin tree + one compare; the 3-SETP/10-SEL insert runs only when
// min of the 4 beats the current 3rd best (~8% of warp-iterations).
// Selection order and strict-< tie-break identical to the branchless version.
// ---------------------------------------------------------------------------
__global__ void __launch_bounds__(256) knn_interp_kernel(
    const float* __restrict__ p1, const float* __restrict__ p2,
    float* __restrict__ out)
{
    extern __shared__ float4 s[];              // [4096]
    const int batch = blockIdx.y;
    const float* p2b = p2 + (size_t)batch * N2PB * 3;
    for (int j = threadIdx.x; j < N2PB; j += 256)
        s[j] = make_float4(p2b[3 * j], p2b[3 * j + 1], p2b[3 * j + 2], 0.f);
    __syncthreads();

    const int ng = batch * N1PB + blockIdx.x * 256 + threadIdx.x;
    const float qx = p1[3 * ng], qy = p1[3 * ng + 1], qz = p1[3 * ng + 2];

    float a0 = 3.4e38f, a1 = 3.4e38f, a2 = 3.4e38f;
    int   i0 = 0, i1 = 0, i2 = 0;

#pragma unroll 1
    for (int j = 0; j < N2PB; j += 4) {
        float d2v[4];
#pragma unroll
        for (int k = 0; k < 4; k++) {
            float4 sp = s[j + k];
            float dx = qx - sp.x, dy = qy - sp.y, dz = qz - sp.z;
            d2v[k] = fmaf(dx, dx, fmaf(dy, dy, dz * dz));
        }
        float m = fminf(fminf(d2v[0], d2v[1]), fminf(d2v[2], d2v[3]));
        if (m < a2) {
#pragma unroll
            for (int k = 0; k < 4; k++) {
                float d2 = d2v[k];
                bool c0 = d2 < a0, c1 = d2 < a1, c2 = d2 < a2;
                a2 = c1 ? a1 : (c2 ? d2 : a2);  i2 = c1 ? i1 : (c2 ? (j + k) : i2);
                a1 = c0 ? a0 : (c1 ? d2 : a1);  i1 = c0 ? i0 : (c1 ? (j + k) : i1);
                a0 = c0 ? d2 : a0;              i0 = c0 ? (j + k) : i0;
            }
        }
    }

    float w0 = 1.f / (a0 + 1e-8f);
    float w1 = 1.f / (a1 + 1e-8f);
    float w2 = 1.f / (a2 + 1e-8f);
    float inv = 1.f / (w0 + w1 + w2);
    w0 *= inv; w1 *= inv; w2 *= inv;

    const float4* f0 = (const float4*)(g_y2t + (size_t)(batch * N2PB + i0) * CV);
    const float4* f1 = (const float4*)(g_y2t + (size_t)(batch * N2PB + i1) * CV);
    const float4* f2 = (const float4*)(g_y2t + (size_t)(batch * N2PB + i2) * CV);
    float* op = out + ng;

#pragma unroll 4
    for (int c4 = 0; c4 < CV / 4; c4++) {
        float4 a = f0[c4], b = f1[c4], c = f2[c4];
        op[(size_t)(4 * c4 + 0) * N1TOT] += w0 * a.x + w1 * b.x + w2 * c.x;
        op[(size_t)(4 * c4 + 1) * N1TOT] += w0 * a.y + w1 * b.y + w2 * c.y;
        op[(size_t)(4 * c4 + 2) * N1TOT] += w0 * a.z + w1 * b.z + w2 * c.z;
        op[(size_t)(4 * c4 + 3) * N1TOT] += w0 * a.w + w1 * b.w + w2 * c.w;
    }
}

// ---------------------------------------------------------------------------
extern "C" void kernel_launch(void* const* d_in, const int* in_sizes, int n_in,
                              void* d_out, int out_size)
{
    const float* p1  = (const float*)d_in[0];
    const float* x1  = (const float*)d_in[1];
    const float* p2  = (const float*)d_in[3];
    const float* x2  = (const float*)d_in[4];
    const float* w1f = (const float*)d_in[6];
    const float* w1d = (const float*)d_in[7];
    const float* w2f = (const float*)d_in[8];
    const float* w2d = (const float*)d_in[9];
    float* out = (float*)d_out;

    const int SVN = (2 * 32 * WS_STRIDE + 32 * 32 * 4) * 4;  // 33280 B
    const int S3  = N2PB * 16;                               // 65536 B

    cudaFuncSetAttribute((const void*)knn_interp_kernel,
                         cudaFuncAttributeMaxDynamicSharedMemorySize, S3);

    // y1 = VN(x1) -> out (base term)
    vn_kernel<64, false><<<N1TOT / 32, 256, SVN>>>(x1, w1f, w1d, out, N1TOT);
    // y2 = VN(x2) -> g_y2t (point-major)
    vn_kernel<128, true><<<N2TOT / 32, 256, SVN>>>(x2, w2f, w2d, nullptr, N2TOT);
    // out += knn-interp(y2)
    knn_interp_kernel<<<dim3(N1PB / 256, 4), 256, S3>>>(p1, p2, out);
}

// round 6
// speedup vs baseline: 1.3730x; 1.1172x over previous
#include <cuda_runtime.h>
#include <cuda_bf16.h>

// Problem constants (fixed by the dataset instance)
#define N1TOT 65536
#define N2TOT 16384
#define N1PB  16384
#define N2PB  4096
#define CV    192   // Cout*3

typedef unsigned long long ull;

// Scratch: y2 in point-major layout [n][c*3+v]
__device__ float g_y2t[N2TOT * CV];

// ---- packed fp32x2 helpers (Blackwell) ------------------------------------
__device__ __forceinline__ ull f2fma(ull a, ull b, ull c) {
    ull d; asm("fma.rn.f32x2 %0, %1, %2, %3;" : "=l"(d) : "l"(a), "l"(b), "l"(c));
    return d;
}
__device__ __forceinline__ ull f2add(ull a, ull b) {
    ull d; asm("add.rn.f32x2 %0, %1, %2;" : "=l"(d) : "l"(a), "l"(b));
    return d;
}
__device__ __forceinline__ ull f2mul(ull a, ull b) {
    ull d; asm("mul.rn.f32x2 %0, %1, %2;" : "=l"(d) : "l"(a), "l"(b));
    return d;
}
__device__ __forceinline__ void f2unpack(ull p, float& lo, float& hi) {
    asm("mov.b64 {%0, %1}, %2;" : "=f"(lo), "=f"(hi) : "l"(p));
}
__device__ __forceinline__ ull f2pack(float lo, float hi) {
    ull d; asm("mov.b64 %0, {%1, %2};" : "=l"(d) : "f"(lo), "f"(hi));
    return d;
}

// ---------------------------------------------------------------------------
// Fused VN linear+leakyrelu for BOTH layers in one launch.
//   blocks [0,512)    : layer2 (x2, CIN=128, N=16384) -> g_y2t point-major
//   blocks [512,2560) : layer1 (x1, CIN=64,  N=65536) -> out channel-major
// Per block: 32 points, 256 thr = 8 og x 32 lanes; thread: 8 outs x 1 point.
// Accumulators are f32x2 pairs (P,D); b-operand is the (wf,wd) pair straight
// from smem; a-operand is (x,x) duplicated at staging. 24 FFMA2/channel.
// ---------------------------------------------------------------------------
#define WS2 66   // float2 stride per channel row (528B, 16B-aligned)

__global__ void __launch_bounds__(256, 3) vn_fused_kernel(
    const float* __restrict__ x1, const float* __restrict__ w1f,
    const float* __restrict__ w1d,
    const float* __restrict__ x2, const float* __restrict__ w2f,
    const float* __restrict__ w2d,
    float* __restrict__ out)
{
    extern __shared__ float sm[];
    ull* ws = (ull*)sm;               // [32][WS2]  (wf,wd) pairs
    ull* xs = ws + 32 * WS2;          // [32][3][32] (x,x) dup pairs
    float2* wsf2 = (float2*)ws;
    float2* xsf2 = (float2*)xs;

    const int tid = threadIdx.x;
    const int p  = tid & 31;
    const int og = tid >> 5;
    const bool is2 = blockIdx.x < 512;
    const float* x  = is2 ? x2  : x1;
    const float* wf = is2 ? w2f : w1f;
    const float* wd = is2 ? w2d : w1d;
    const int CIN = is2 ? 128 : 64;
    const int N   = is2 ? N2TOT : N1TOT;
    const int n0  = (is2 ? blockIdx.x : blockIdx.x - 512) * 32;

    ull pd[8][3];
#pragma unroll
    for (int i = 0; i < 8; i++)
#pragma unroll
        for (int v = 0; v < 3; v++) pd[i][v] = 0ull;

    for (int c0 = 0; c0 < CIN; c0 += 32) {
        __syncthreads();   // previous chunk fully consumed
        for (int i = tid; i < 2048; i += 256) {
            int o = i >> 5, cc = i & 31;
            wsf2[cc * WS2 + o] =
                make_float2(wf[o * CIN + c0 + cc], wd[o * CIN + c0 + cc]);
        }
        for (int i = tid; i < 3072; i += 256) {
            int v = i >> 10, cc = (i >> 5) & 31, pp = i & 31;
            float xv = x[(size_t)(c0 + cc) * 3 * N + (size_t)v * N + (n0 + pp)];
            xsf2[(cc * 3 + v) * 32 + pp] = make_float2(xv, xv);
        }
        __syncthreads();

        const ulonglong2* wsv = (const ulonglong2*)ws;
#pragma unroll 4
        for (int cc = 0; cc < 32; cc++) {
            ull xv0 = xs[(cc * 3 + 0) * 32 + p];
            ull xv1 = xs[(cc * 3 + 1) * 32 + p];
            ull xv2 = xs[(cc * 3 + 2) * 32 + p];
#pragma unroll
            for (int k = 0; k < 4; k++) {
                ulonglong2 w2 = wsv[cc * (WS2 / 2) + og * 4 + k];
                int i = 2 * k;
                pd[i][0]   = f2fma(xv0, w2.x, pd[i][0]);
                pd[i][1]   = f2fma(xv1, w2.x, pd[i][1]);
                pd[i][2]   = f2fma(xv2, w2.x, pd[i][2]);
                pd[i+1][0] = f2fma(xv0, w2.y, pd[i+1][0]);
                pd[i+1][1] = f2fma(xv1, w2.y, pd[i+1][1]);
                pd[i+1][2] = f2fma(xv2, w2.y, pd[i+1][2]);
            }
        }
    }

    // nonlinearity: dot>=0 -> P ; dot<0 -> P - 0.8*(dot/(|D|^2+1e-6))*D
    float val[8][3];
#pragma unroll
    for (int i = 0; i < 8; i++) {
        float P[3], D[3];
#pragma unroll
        for (int v = 0; v < 3; v++) f2unpack(pd[i][v], P[v], D[v]);
        float dot = P[0] * D[0] + P[1] * D[1] + P[2] * D[2];
        float dd  = D[0] * D[0] + D[1] * D[1] + D[2] * D[2];
        float coef = (dot < 0.f) ? (0.8f * dot / (dd + 1e-6f)) : 0.f;
        val[i][0] = P[0] - coef * D[0];
        val[i][1] = P[1] - coef * D[1];
        val[i][2] = P[2] - coef * D[2];
    }

    if (!is2) {
#pragma unroll
        for (int i = 0; i < 8; i++) {
            int o = og * 8 + i;
#pragma unroll
            for (int v = 0; v < 3; v++)
                out[(size_t)(o * 3 + v) * N + (n0 + p)] = val[i][v];
        }
    } else {
        __syncthreads();                  // done with ws/xs; reuse as transpose buf
        float* tb = sm;                   // [32][193] (pad -> conflict free)
#pragma unroll
        for (int i = 0; i < 8; i++) {
            int o = og * 8 + i;
#pragma unroll
            for (int v = 0; v < 3; v++)
                tb[p * 193 + (o * 3 + v)] = val[i][v];
        }
        __syncthreads();
        for (int i = tid; i < 32 * CV; i += 256) {
            int pp = i / CV, cv = i - pp * CV;
            g_y2t[(size_t)(n0 + pp) * CV + cv] = tb[pp * 193 + cv];
        }
    }
}

// ---------------------------------------------------------------------------
// Brute-force 3-NN + inverse-sq-dist interpolation + add into out.
// SoA coords in smem; f32x2 distances (2 candidates per packed op chain);
// guard per 8 candidates, then per-scalar guard before the exact fp32
// strict-< sorted insert (bit-identical selection to the always-insert form).
// ---------------------------------------------------------------------------
__global__ void __launch_bounds__(256) knn_interp_kernel(
    const float* __restrict__ p1, const float* __restrict__ p2,
    float* __restrict__ out)
{
    extern __shared__ float s[];               // sx[4096] sy[4096] sz[4096]
    float* sx = s;
    float* sy = s + N2PB;
    float* sz = s + 2 * N2PB;
    const int batch = blockIdx.y;
    const float* p2b = p2 + (size_t)batch * N2PB * 3;
    for (int j = threadIdx.x; j < N2PB; j += 256) {
        sx[j] = p2b[3 * j];
        sy[j] = p2b[3 * j + 1];
        sz[j] = p2b[3 * j + 2];
    }
    __syncthreads();

    const int ng = batch * N1PB + blockIdx.x * 256 + threadIdx.x;
    const float qx = p1[3 * ng], qy = p1[3 * ng + 1], qz = p1[3 * ng + 2];
    const ull nqx2 = f2pack(-qx, -qx);
    const ull nqy2 = f2pack(-qy, -qy);
    const ull nqz2 = f2pack(-qz, -qz);

    float a0 = 3.4e38f, a1 = 3.4e38f, a2 = 3.4e38f;
    int   i0 = 0, i1 = 0, i2 = 0;

    const ulonglong2* sx2 = (const ulonglong2*)sx;
    const ulonglong2* sy2 = (const ulonglong2*)sy;
    const ulonglong2* sz2 = (const ulonglong2*)sz;

#pragma unroll 2
    for (int j = 0; j < N2PB; j += 8) {
        ulonglong2 xa = sx2[j >> 2], xb = sx2[(j >> 2) + 1];
        ulonglong2 ya = sy2[j >> 2], yb = sy2[(j >> 2) + 1];
        ulonglong2 za = sz2[j >> 2], zb = sz2[(j >> 2) + 1];
        ull dp[4];
        {
            ull dx = f2add(xa.x, nqx2), dy = f2add(ya.x, nqy2), dz = f2add(za.x, nqz2);
            dp[0] = f2fma(dz, dz, f2fma(dy, dy, f2mul(dx, dx)));
        }
        {
            ull dx = f2add(xa.y, nqx2), dy = f2add(ya.y, nqy2), dz = f2add(za.y, nqz2);
            dp[1] = f2fma(dz, dz, f2fma(dy, dy, f2mul(dx, dx)));
        }
        {
            ull dx = f2add(xb.x, nqx2), dy = f2add(yb.x, nqy2), dz = f2add(zb.x, nqz2);
            dp[2] = f2fma(dz, dz, f2fma(dy, dy, f2mul(dx, dx)));
        }
        {
            ull dx = f2add(xb.y, nqx2), dy = f2add(yb.y, nqy2), dz = f2add(zb.y, nqz2);
            dp[3] = f2fma(dz, dz, f2fma(dy, dy, f2mul(dx, dx)));
        }
        float d2s[8];
        f2unpack(dp[0], d2s[0], d2s[1]);
        f2unpack(dp[1], d2s[2], d2s[3]);
        f2unpack(dp[2], d2s[4], d2s[5]);
        f2unpack(dp[3], d2s[6], d2s[7]);
        float m = fminf(fminf(fminf(d2s[0], d2s[1]), fminf(d2s[2], d2s[3])),
                        fminf(fminf(d2s[4], d2s[5]), fminf(d2s[6], d2s[7])));
        if (m < a2) {
#pragma unroll
            for (int k = 0; k < 8; k++) {
                float d2 = d2s[k];
                if (d2 < a2) {
                    bool c0 = d2 < a0, c1 = d2 < a1;
                    a2 = c1 ? a1 : d2;  i2 = c1 ? i1 : (j + k);
                    a1 = c0 ? a0 : (c1 ? d2 : a1);  i1 = c0 ? i0 : (c1 ? (j + k) : i1);
                    a0 = c0 ? d2 : a0;  i0 = c0 ? (j + k) : i0;
                }
            }
        }
    }

    float w0 = 1.f / (a0 + 1e-8f);
    float w1 = 1.f / (a1 + 1e-8f);
    float w2 = 1.f / (a2 + 1e-8f);
    float inv = 1.f / (w0 + w1 + w2);
    w0 *= inv; w1 *= inv; w2 *= inv;

    const float4* f0 = (const float4*)(g_y2t + (size_t)(batch * N2PB + i0) * CV);
    const float4* f1 = (const float4*)(g_y2t + (size_t)(batch * N2PB + i1) * CV);
    const float4* f2 = (const float4*)(g_y2t + (size_t)(batch * N2PB + i2) * CV);
    float* op = out + ng;

#pragma unroll 4
    for (int c4 = 0; c4 < CV / 4; c4++) {
        float4 a = f0[c4], b = f1[c4], c = f2[c4];
        op[(size_t)(4 * c4 + 0) * N1TOT] += w0 * a.x + w1 * b.x + w2 * c.x;
        op[(size_t)(4 * c4 + 1) * N1TOT] += w0 * a.y + w1 * b.y + w2 * c.y;
        op[(size_t)(4 * c4 + 2) * N1TOT] += w0 * a.z + w1 * b.z + w2 * c.z;
        op[(size_t)(4 * c4 + 3) * N1TOT] += w0 * a.w + w1 * b.w + w2 * c.w;
    }
}

// ---------------------------------------------------------------------------
extern "C" void kernel_launch(void* const* d_in, const int* in_sizes, int n_in,
                              void* d_out, int out_size)
{
    const float* p1  = (const float*)d_in[0];
    const float* x1  = (const float*)d_in[1];
    const float* p2  = (const float*)d_in[3];
    const float* x2  = (const float*)d_in[4];
    const float* w1f = (const float*)d_in[6];
    const float* w1d = (const float*)d_in[7];
    const float* w2f = (const float*)d_in[8];
    const float* w2d = (const float*)d_in[9];
    float* out = (float*)d_out;

    const int SVN = (32 * WS2 + 32 * 3 * 32) * 8;   // 41472 B
    const int S3  = 3 * N2PB * 4;                   // 49152 B

    cudaFuncSetAttribute((const void*)vn_fused_kernel,
                         cudaFuncAttributeMaxDynamicSharedMemorySize, SVN);
    cudaFuncSetAttribute((const void*)knn_interp_kernel,
                         cudaFuncAttributeMaxDynamicSharedMemorySize, S3);

    // blocks [0,512): y2 -> g_y2t ; blocks [512,2560): y1 -> out
    vn_fused_kernel<<<2560, 256, SVN>>>(x1, w1f, w1d, x2, w2f, w2d, out);
    // out += knn-interp(y2)
    knn_interp_kernel<<<dim3(N1PB / 256, 4), 256, S3>>>(p1, p2, out);
}

// round 7
// speedup vs baseline: 1.4205x; 1.0346x over previous
#include <cuda_runtime.h>
#include <cuda_bf16.h>

// Problem constants (fixed by the dataset instance)
#define N1TOT 65536
#define N2TOT 16384
#define N1PB  16384
#define N2PB  4096
#define CV    192   // Cout*3
#define NSPLIT 4
#define NCSPL  (N2PB / NSPLIT)   // 1024 candidates per split

typedef unsigned long long ull;

// Scratch: y2 in point-major layout [n][c*3+v]
__device__ float g_y2t[N2TOT * CV];
// Partial top-3 per (split, rank, query)
__device__ float g_pd[NSPLIT][3][N1TOT];
__device__ int   g_pi[NSPLIT][3][N1TOT];

// ---- packed fp32x2 helpers (Blackwell) ------------------------------------
__device__ __forceinline__ ull f2fma(ull a, ull b, ull c) {
    ull d; asm("fma.rn.f32x2 %0, %1, %2, %3;" : "=l"(d) : "l"(a), "l"(b), "l"(c));
    return d;
}
__device__ __forceinline__ ull f2add(ull a, ull b) {
    ull d; asm("add.rn.f32x2 %0, %1, %2;" : "=l"(d) : "l"(a), "l"(b));
    return d;
}
__device__ __forceinline__ ull f2mul(ull a, ull b) {
    ull d; asm("mul.rn.f32x2 %0, %1, %2;" : "=l"(d) : "l"(a), "l"(b));
    return d;
}
__device__ __forceinline__ void f2unpack(ull p, float& lo, float& hi) {
    asm("mov.b64 {%0, %1}, %2;" : "=f"(lo), "=f"(hi) : "l"(p));
}
__device__ __forceinline__ ull f2pack(float lo, float hi) {
    ull d; asm("mov.b64 %0, {%1, %2};" : "=l"(d) : "f"(lo), "f"(hi));
    return d;
}

// ---------------------------------------------------------------------------
// Fused VN linear+leakyrelu for BOTH layers in one launch.
//   blocks [0,512)    : layer2 (x2, CIN=128, N=16384) -> g_y2t point-major
//   blocks [512,2560) : layer1 (x1, CIN=64,  N=65536) -> out channel-major
// f32x2 accumulators hold (P,D); b-operand = smem (wf,wd) pair; a = (x,x).
// ---------------------------------------------------------------------------
#define WS2 66   // float2 stride per channel row (528B, 16B-aligned)

__global__ void __launch_bounds__(256, 3) vn_fused_kernel(
    const float* __restrict__ x1, const float* __restrict__ w1f,
    const float* __restrict__ w1d,
    const float* __restrict__ x2, const float* __restrict__ w2f,
    const float* __restrict__ w2d,
    float* __restrict__ out)
{
    extern __shared__ float sm[];
    ull* ws = (ull*)sm;               // [32][WS2]  (wf,wd) pairs
    ull* xs = ws + 32 * WS2;          // [32][3][32] (x,x) dup pairs
    float2* wsf2 = (float2*)ws;
    float2* xsf2 = (float2*)xs;

    const int tid = threadIdx.x;
    const int p  = tid & 31;
    const int og = tid >> 5;
    const bool is2 = blockIdx.x < 512;
    const float* x  = is2 ? x2  : x1;
    const float* wf = is2 ? w2f : w1f;
    const float* wd = is2 ? w2d : w1d;
    const int CIN = is2 ? 128 : 64;
    const int N   = is2 ? N2TOT : N1TOT;
    const int n0  = (is2 ? blockIdx.x : blockIdx.x - 512) * 32;

    ull pd[8][3];
#pragma unroll
    for (int i = 0; i < 8; i++)
#pragma unroll
        for (int v = 0; v < 3; v++) pd[i][v] = 0ull;

    for (int c0 = 0; c0 < CIN; c0 += 32) {
        __syncthreads();   // previous chunk fully consumed
        for (int i = tid; i < 2048; i += 256) {
            int o = i >> 5, cc = i & 31;
            wsf2[cc * WS2 + o] =
                make_float2(wf[o * CIN + c0 + cc], wd[o * CIN + c0 + cc]);
        }
        for (int i = tid; i < 3072; i += 256) {
            int v = i >> 10, cc = (i >> 5) & 31, pp = i & 31;
            float xv = x[(size_t)(c0 + cc) * 3 * N + (size_t)v * N + (n0 + pp)];
            xsf2[(cc * 3 + v) * 32 + pp] = make_float2(xv, xv);
        }
        __syncthreads();

        const ulonglong2* wsv = (const ulonglong2*)ws;
#pragma unroll 4
        for (int cc = 0; cc < 32; cc++) {
            ull xv0 = xs[(cc * 3 + 0) * 32 + p];
            ull xv1 = xs[(cc * 3 + 1) * 32 + p];
            ull xv2 = xs[(cc * 3 + 2) * 32 + p];
#pragma unroll
            for (int k = 0; k < 4; k++) {
                ulonglong2 w2 = wsv[cc * (WS2 / 2) + og * 4 + k];
                int i = 2 * k;
                pd[i][0]   = f2fma(xv0, w2.x, pd[i][0]);
                pd[i][1]   = f2fma(xv1, w2.x, pd[i][1]);
                pd[i][2]   = f2fma(xv2, w2.x, pd[i][2]);
                pd[i+1][0] = f2fma(xv0, w2.y, pd[i+1][0]);
                pd[i+1][1] = f2fma(xv1, w2.y, pd[i+1][1]);
                pd[i+1][2] = f2fma(xv2, w2.y, pd[i+1][2]);
            }
        }
    }

    // nonlinearity: dot>=0 -> P ; dot<0 -> P - 0.8*(dot/(|D|^2+1e-6))*D
    float val[8][3];
#pragma unroll
    for (int i = 0; i < 8; i++) {
        float P[3], D[3];
#pragma unroll
        for (int v = 0; v < 3; v++) f2unpack(pd[i][v], P[v], D[v]);
        float dot = P[0] * D[0] + P[1] * D[1] + P[2] * D[2];
        float dd  = D[0] * D[0] + D[1] * D[1] + D[2] * D[2];
        float coef = (dot < 0.f) ? (0.8f * dot / (dd + 1e-6f)) : 0.f;
        val[i][0] = P[0] - coef * D[0];
        val[i][1] = P[1] - coef * D[1];
        val[i][2] = P[2] - coef * D[2];
    }

    if (!is2) {
#pragma unroll
        for (int i = 0; i < 8; i++) {
            int o = og * 8 + i;
#pragma unroll
            for (int v = 0; v < 3; v++)
                out[(size_t)(o * 3 + v) * N + (n0 + p)] = val[i][v];
        }
    } else {
        __syncthreads();                  // done with ws/xs; reuse as transpose buf
        float* tb = sm;                   // [32][193] (pad -> conflict free)
#pragma unroll
        for (int i = 0; i < 8; i++) {
            int o = og * 8 + i;
#pragma unroll
            for (int v = 0; v < 3; v++)
                tb[p * 193 + (o * 3 + v)] = val[i][v];
        }
        __syncthreads();
        for (int i = tid; i < 32 * CV; i += 256) {
            int pp = i / CV, cv = i - pp * CV;
            g_y2t[(size_t)(n0 + pp) * CV + cv] = tb[pp * 193 + cv];
        }
    }
}

// ---------------------------------------------------------------------------
// Phase 1: partial 3-NN over a 1024-candidate split.
// Grid (64, batch=4, split=4) = 1024 blocks -> ~7 blocks/SM, high occupancy.
// f32x2 distances; strict-< sorted insert (exact fp32, same order as R6).
// ---------------------------------------------------------------------------
__global__ void __launch_bounds__(256) knn_scan_kernel(
    const float* __restrict__ p1, const float* __restrict__ p2)
{
    extern __shared__ float s[];               // sx/sy/sz [1024] each
    float* sx = s;
    float* sy = s + NCSPL;
    float* sz = s + 2 * NCSPL;
    const int batch = blockIdx.y;
    const int split = blockIdx.z;
    const int jbase = split * NCSPL;
    const float* p2b = p2 + (size_t)(batch * N2PB + jbase) * 3;
    for (int j = threadIdx.x; j < NCSPL; j += 256) {
        sx[j] = p2b[3 * j];
        sy[j] = p2b[3 * j + 1];
        sz[j] = p2b[3 * j + 2];
    }
    __syncthreads();

    const int ng = batch * N1PB + blockIdx.x * 256 + threadIdx.x;
    const float qx = p1[3 * ng], qy = p1[3 * ng + 1], qz = p1[3 * ng + 2];
    const ull nqx2 = f2pack(-qx, -qx);
    const ull nqy2 = f2pack(-qy, -qy);
    const ull nqz2 = f2pack(-qz, -qz);

    float a0 = 3.4e38f, a1 = 3.4e38f, a2 = 3.4e38f;
    int   i0 = 0, i1 = 0, i2 = 0;

    const ulonglong2* sx2 = (const ulonglong2*)sx;
    const ulonglong2* sy2 = (const ulonglong2*)sy;
    const ulonglong2* sz2 = (const ulonglong2*)sz;

#pragma unroll 2
    for (int j = 0; j < NCSPL; j += 8) {
        ulonglong2 xa = sx2[j >> 2], xb = sx2[(j >> 2) + 1];
        ulonglong2 ya = sy2[j >> 2], yb = sy2[(j >> 2) + 1];
        ulonglong2 za = sz2[j >> 2], zb = sz2[(j >> 2) + 1];
        ull dp[4];
        {
            ull dx = f2add(xa.x, nqx2), dy = f2add(ya.x, nqy2), dz = f2add(za.x, nqz2);
            dp[0] = f2fma(dz, dz, f2fma(dy, dy, f2mul(dx, dx)));
        }
        {
            ull dx = f2add(xa.y, nqx2), dy = f2add(ya.y, nqy2), dz = f2add(za.y, nqz2);
            dp[1] = f2fma(dz, dz, f2fma(dy, dy, f2mul(dx, dx)));
        }
        {
            ull dx = f2add(xb.x, nqx2), dy = f2add(yb.x, nqy2), dz = f2add(zb.x, nqz2);
            dp[2] = f2fma(dz, dz, f2fma(dy, dy, f2mul(dx, dx)));
        }
        {
            ull dx = f2add(xb.y, nqx2), dy = f2add(yb.y, nqy2), dz = f2add(zb.y, nqz2);
            dp[3] = f2fma(dz, dz, f2fma(dy, dy, f2mul(dx, dx)));
        }
        float d2s[8];
        f2unpack(dp[0], d2s[0], d2s[1]);
        f2unpack(dp[1], d2s[2], d2s[3]);
        f2unpack(dp[2], d2s[4], d2s[5]);
        f2unpack(dp[3], d2s[6], d2s[7]);
        float m = fminf(fminf(fminf(d2s[0], d2s[1]), fminf(d2s[2], d2s[3])),
                        fminf(fminf(d2s[4], d2s[5]), fminf(d2s[6], d2s[7])));
        if (m < a2) {
#pragma unroll
            for (int k = 0; k < 8; k++) {
                float d2 = d2s[k];
                if (d2 < a2) {
                    bool c0 = d2 < a0, c1 = d2 < a1;
                    a2 = c1 ? a1 : d2;  i2 = c1 ? i1 : (j + k);
                    a1 = c0 ? a0 : (c1 ? d2 : a1);  i1 = c0 ? i0 : (c1 ? (j + k) : i1);
                    a0 = c0 ? d2 : a0;  i0 = c0 ? (j + k) : i0;
                }
            }
        }
    }

    g_pd[split][0][ng] = a0; g_pi[split][0][ng] = jbase + i0;
    g_pd[split][1][ng] = a1; g_pi[split][1][ng] = jbase + i1;
    g_pd[split][2][ng] = a2; g_pi[split][2][ng] = jbase + i2;
}

// ---------------------------------------------------------------------------
// Phase 2: merge 4 partial top-3s (split order -> first-seen-wins on ties,
// identical to a sequential scan), then interp gather + RMW into out.
// ---------------------------------------------------------------------------
__global__ void __launch_bounds__(256) knn_merge_kernel(float* __restrict__ out)
{
    const int ng = blockIdx.x * 256 + threadIdx.x;
    const int batch = ng >> 14;   // / N1PB

    float a0 = 3.4e38f, a1 = 3.4e38f, a2 = 3.4e38f;
    int   i0 = 0, i1 = 0, i2 = 0;
#pragma unroll
    for (int s = 0; s < NSPLIT; s++) {
#pragma unroll
        for (int k = 0; k < 3; k++) {
            float d2 = g_pd[s][k][ng];
            int   jj = g_pi[s][k][ng];
            bool c0 = d2 < a0, c1 = d2 < a1, c2 = d2 < a2;
            a2 = c1 ? a1 : (c2 ? d2 : a2);  i2 = c1 ? i1 : (c2 ? jj : i2);
            a1 = c0 ? a0 : (c1 ? d2 : a1);  i1 = c0 ? i0 : (c1 ? jj : i1);
            a0 = c0 ? d2 : a0;              i0 = c0 ? jj : i0;
        }
    }

    float w0 = 1.f / (a0 + 1e-8f);
    float w1 = 1.f / (a1 + 1e-8f);
    float w2 = 1.f / (a2 + 1e-8f);
    float inv = 1.f / (w0 + w1 + w2);
    w0 *= inv; w1 *= inv; w2 *= inv;

    const float4* f0 = (const float4*)(g_y2t + (size_t)(batch * N2PB + i0) * CV);
    const float4* f1 = (const float4*)(g_y2t + (size_t)(batch * N2PB + i1) * CV);
    const float4* f2 = (const float4*)(g_y2t + (size_t)(batch * N2PB + i2) * CV);
    float* op = out + ng;

#pragma unroll 4
    for (int c4 = 0; c4 < CV / 4; c4++) {
        float4 a = f0[c4], b = f1[c4], c = f2[c4];
        op[(size_t)(4 * c4 + 0) * N1TOT] += w0 * a.x + w1 * b.x + w2 * c.x;
        op[(size_t)(4 * c4 + 1) * N1TOT] += w0 * a.y + w1 * b.y + w2 * c.y;
        op[(size_t)(4 * c4 + 2) * N1TOT] += w0 * a.z + w1 * b.z + w2 * c.z;
        op[(size_t)(4 * c4 + 3) * N1TOT] += w0 * a.w + w1 * b.w + w2 * c.w;
    }
}

// ---------------------------------------------------------------------------
extern "C" void kernel_launch(void* const* d_in, const int* in_sizes, int n_in,
                              void* d_out, int out_size)
{
    const float* p1  = (const float*)d_in[0];
    const float* x1  = (const float*)d_in[1];
    const float* p2  = (const float*)d_in[3];
    const float* x2  = (const float*)d_in[4];
    const float* w1f = (const float*)d_in[6];
    const float* w1d = (const float*)d_in[7];
    const float* w2f = (const float*)d_in[8];
    const float* w2d = (const float*)d_in[9];
    float* out = (float*)d_out;

    const int SVN = (32 * WS2 + 32 * 3 * 32) * 8;   // 41472 B
    const int SSC = 3 * NCSPL * 4;                  // 12288 B

    cudaFuncSetAttribute((const void*)vn_fused_kernel,
                         cudaFuncAttributeMaxDynamicSharedMemorySize, SVN);

    // blocks [0,512): y2 -> g_y2t ; blocks [512,2560): y1 -> out
    vn_fused_kernel<<<2560, 256, SVN>>>(x1, w1f, w1d, x2, w2f, w2d, out);
    // partial 3-NN per candidate split (runs concurrently-independent of vn
    // stream-order; same stream so it serializes after vn, which is fine:
    // it only needs p1/p2)
    knn_scan_kernel<<<dim3(N1PB / 256, 4, NSPLIT), 256, SSC>>>(p1, p2);
    // merge partials + interpolate + add into out
    knn_merge_kernel<<<N1TOT / 256, 256>>>(out);
}

// round 9
// speedup vs baseline: 1.8627x; 1.3113x over previous
#include <cuda_runtime.h>
#include <cuda_bf16.h>

// Problem constants (fixed by the dataset instance)
#define N1TOT 65536
#define N2TOT 16384
#define N1PB  16384
#define N2PB  4096
#define CV    192   // Cout*3
#define G     8      // bins per axis
#define NBIN  512    // per batch
#define NBINT 2048   // total (4 batches)
#define BINW  0.125f

typedef unsigned long long ull;

// Scratch
__device__ float  g_y2t[N2TOT * CV];   // y2 point-major [n][c*3+v]
__device__ int    g_cnt2[NBINT];       // p2 bin counts -> fill cursors
__device__ int    g_start2[NBINT + 1];
__device__ float4 g_b2[N2TOT];         // binned p2: (x,y,z, local_idx bits)
__device__ int    g_cnt1[NBINT];
__device__ int    g_start1[NBINT + 1];
__device__ float4 g_b1[N1TOT];         // binned p1: (x,y,z, orig_ng bits)
__device__ float  g_kd[3][N1TOT];      // top-3 distances per query
__device__ int    g_ki[3][N1TOT];      // top-3 local indices per query

// ---- packed fp32x2 helpers (Blackwell) ------------------------------------
__device__ __forceinline__ ull f2fma(ull a, ull b, ull c) {
    ull d; asm("fma.rn.f32x2 %0, %1, %2, %3;" : "=l"(d) : "l"(a), "l"(b), "l"(c));
    return d;
}
__device__ __forceinline__ void f2unpack(ull p, float& lo, float& hi) {
    asm("mov.b64 {%0, %1}, %2;" : "=f"(lo), "=f"(hi) : "l"(p));
}

// ---------------------------------------------------------------------------
// Fused VN linear+leakyrelu for BOTH layers in one launch. (unchanged R7)
// ---------------------------------------------------------------------------
#define WS2 66

__global__ void __launch_bounds__(256, 3) vn_fused_kernel(
    const float* __restrict__ x1, const float* __restrict__ w1f,
    const float* __restrict__ w1d,
    const float* __restrict__ x2, const float* __restrict__ w2f,
    const float* __restrict__ w2d,
    float* __restrict__ out)
{
    extern __shared__ float sm[];
    ull* ws = (ull*)sm;
    ull* xs = ws + 32 * WS2;
    float2* wsf2 = (float2*)ws;
    float2* xsf2 = (float2*)xs;

    const int tid = threadIdx.x;
    const int p  = tid & 31;
    const int og = tid >> 5;
    const bool is2 = blockIdx.x < 512;
    const float* x  = is2 ? x2  : x1;
    const float* wf = is2 ? w2f : w1f;
    const float* wd = is2 ? w2d : w1d;
    const int CIN = is2 ? 128 : 64;
    const int N   = is2 ? N2TOT : N1TOT;
    const int n0  = (is2 ? blockIdx.x : blockIdx.x - 512) * 32;

    ull pd[8][3];
#pragma unroll
    for (int i = 0; i < 8; i++)
#pragma unroll
        for (int v = 0; v < 3; v++) pd[i][v] = 0ull;

    for (int c0 = 0; c0 < CIN; c0 += 32) {
        __syncthreads();
        for (int i = tid; i < 2048; i += 256) {
            int o = i >> 5, cc = i & 31;
            wsf2[cc * WS2 + o] =
                make_float2(wf[o * CIN + c0 + cc], wd[o * CIN + c0 + cc]);
        }
        for (int i = tid; i < 3072; i += 256) {
            int v = i >> 10, cc = (i >> 5) & 31, pp = i & 31;
            float xv = x[(size_t)(c0 + cc) * 3 * N + (size_t)v * N + (n0 + pp)];
            xsf2[(cc * 3 + v) * 32 + pp] = make_float2(xv, xv);
        }
        __syncthreads();

        const ulonglong2* wsv = (const ulonglong2*)ws;
#pragma unroll 4
        for (int cc = 0; cc < 32; cc++) {
            ull xv0 = xs[(cc * 3 + 0) * 32 + p];
            ull xv1 = xs[(cc * 3 + 1) * 32 + p];
            ull xv2 = xs[(cc * 3 + 2) * 32 + p];
#pragma unroll
            for (int k = 0; k < 4; k++) {
                ulonglong2 w2 = wsv[cc * (WS2 / 2) + og * 4 + k];
                int i = 2 * k;
                pd[i][0]   = f2fma(xv0, w2.x, pd[i][0]);
                pd[i][1]   = f2fma(xv1, w2.x, pd[i][1]);
                pd[i][2]   = f2fma(xv2, w2.x, pd[i][2]);
                pd[i+1][0] = f2fma(xv0, w2.y, pd[i+1][0]);
                pd[i+1][1] = f2fma(xv1, w2.y, pd[i+1][1]);
                pd[i+1][2] = f2fma(xv2, w2.y, pd[i+1][2]);
            }
        }
    }

    float val[8][3];
#pragma unroll
    for (int i = 0; i < 8; i++) {
        float P[3], D[3];
#pragma unroll
        for (int v = 0; v < 3; v++) f2unpack(pd[i][v], P[v], D[v]);
        float dot = P[0] * D[0] + P[1] * D[1] + P[2] * D[2];
        float dd  = D[0] * D[0] + D[1] * D[1] + D[2] * D[2];
        float coef = (dot < 0.f) ? (0.8f * dot / (dd + 1e-6f)) : 0.f;
        val[i][0] = P[0] - coef * D[0];
        val[i][1] = P[1] - coef * D[1];
        val[i][2] = P[2] - coef * D[2];
    }

    if (!is2) {
#pragma unroll
        for (int i = 0; i < 8; i++) {
            int o = og * 8 + i;
#pragma unroll
            for (int v = 0; v < 3; v++)
                out[(size_t)(o * 3 + v) * N + (n0 + p)] = val[i][v];
        }
    } else {
        __syncthreads();
        float* tb = sm;                   // [32][193]
#pragma unroll
        for (int i = 0; i < 8; i++) {
            int o = og * 8 + i;
#pragma unroll
            for (int v = 0; v < 3; v++)
                tb[p * 193 + (o * 3 + v)] = val[i][v];
        }
        __syncthreads();
        for (int i = tid; i < 32 * CV; i += 256) {
            int pp = i / CV, cv = i - pp * CV;
            g_y2t[(size_t)(n0 + pp) * CV + cv] = tb[pp * 193 + cv];
        }
    }
}

// ---------------------------------------------------------------------------
// Spatial binning build: zero -> count -> prefix -> scatter
// ---------------------------------------------------------------------------
__device__ __forceinline__ int bin_of(int batch, float x, float y, float z) {
    int bx = min(G - 1, max(0, (int)(x * 8.0f)));
    int by = min(G - 1, max(0, (int)(y * 8.0f)));
    int bz = min(G - 1, max(0, (int)(z * 8.0f)));
    return batch * NBIN + (bz * G + by) * G + bx;
}

__global__ void zero_kernel() {
    int t = blockIdx.x * 256 + threadIdx.x;
    if (t < NBINT) g_cnt2[t] = 0;
    else if (t < 2 * NBINT) g_cnt1[t - NBINT] = 0;
}

__global__ void bin_count_kernel(const float* __restrict__ p1,
                                 const float* __restrict__ p2) {
    int t = blockIdx.x * 256 + threadIdx.x;
    if (t < N2TOT) {
        float x = p2[3 * t], y = p2[3 * t + 1], z = p2[3 * t + 2];
        atomicAdd(&g_cnt2[bin_of(t >> 12, x, y, z)], 1);
    } else {
        int i = t - N2TOT;           // 0 .. N1TOT-1
        float x = p1[3 * i], y = p1[3 * i + 1], z = p1[3 * i + 2];
        atomicAdd(&g_cnt1[bin_of(i >> 14, x, y, z)], 1);
    }
}

__global__ void prefix_kernel() {
    int* cnt   = blockIdx.x ? g_cnt1 : g_cnt2;
    int* start = blockIdx.x ? g_start1 : g_start2;
    __shared__ int wsum[8];
    int tid = threadIdx.x;               // 256
    int loc[8]; int sum = 0;
#pragma unroll
    for (int k = 0; k < 8; k++) { loc[k] = cnt[tid * 8 + k]; sum += loc[k]; }
    int lane = tid & 31, wid = tid >> 5;
    int v = sum;
#pragma unroll
    for (int o = 1; o < 32; o <<= 1) {
        int t2 = __shfl_up_sync(0xffffffffu, v, o);
        if (lane >= o) v += t2;
    }
    if (lane == 31) wsum[wid] = v;
    __syncthreads();
    int woff = 0;
    for (int k = 0; k < wid; k++) woff += wsum[k];
    int excl = woff + v - sum;
#pragma unroll
    for (int k = 0; k < 8; k++) {
        start[tid * 8 + k] = excl;
        cnt[tid * 8 + k] = excl;         // reuse as scatter cursor
        excl += loc[k];
    }
    if (tid == 255) start[NBINT] = excl;
}

__global__ void bin_scatter_kernel(const float* __restrict__ p1,
                                   const float* __restrict__ p2) {
    int t = blockIdx.x * 256 + threadIdx.x;
    if (t < N2TOT) {
        float x = p2[3 * t], y = p2[3 * t + 1], z = p2[3 * t + 2];
        int pos = atomicAdd(&g_cnt2[bin_of(t >> 12, x, y, z)], 1);
        g_b2[pos] = make_float4(x, y, z, __int_as_float(t & (N2PB - 1)));
    } else {
        int i = t - N2TOT;
        float x = p1[3 * i], y = p1[3 * i + 1], z = p1[3 * i + 2];
        int pos = atomicAdd(&g_cnt1[bin_of(i >> 14, x, y, z)], 1);
        g_b1[pos] = make_float4(x, y, z, __int_as_float(i));
    }
}

// ---------------------------------------------------------------------------
// 3-NN via bins: thread = one (bin-sorted) query; scan 3x3x3 neighborhood
// (9 contiguous runs, x-adjacent bins are contiguous). Exact fp32 strict-<
// insert. Margin test guarantees exactness; rare failures (domain corners)
// fall back to an exact full-batch scan.
// ---------------------------------------------------------------------------
__global__ void __launch_bounds__(256) knn_bin_kernel()
{
    const int t = blockIdx.x * 256 + threadIdx.x;
    float4 q = g_b1[t];
    const int batch = t >> 14;           // batches contiguous in sorted order
    const int orig  = __float_as_int(q.w);
    const float qx = q.x, qy = q.y, qz = q.z;
    int bx = min(G - 1, max(0, (int)(qx * 8.0f)));
    int by = min(G - 1, max(0, (int)(qy * 8.0f)));
    int bz = min(G - 1, max(0, (int)(qz * 8.0f)));

    float a0 = 3.4e38f, a1 = 3.4e38f, a2 = 3.4e38f;
    int   i0 = 0, i1 = 0, i2 = 0;

    const int xlo = max(bx - 1, 0), xhi = min(bx + 1, G - 1);
    const int ylo = max(by - 1, 0), yhi = min(by + 1, G - 1);
    const int zlo = max(bz - 1, 0), zhi = min(bz + 1, G - 1);
    const int base = batch * NBIN;

    for (int z = zlo; z <= zhi; z++) {
        for (int y = ylo; y <= yhi; y++) {
            int b0 = base + (z * G + y) * G + xlo;
            int s = g_start2[b0];
            int e = g_start2[b0 + (xhi - xlo) + 1];
            for (int j = s; j < e; j++) {
                float4 c = g_b2[j];
                float dx = qx - c.x, dy = qy - c.y, dz = qz - c.z;
                float d2 = fmaf(dx, dx, fmaf(dy, dy, dz * dz));
                int idx = __float_as_int(c.w);
                bool c0 = d2 < a0, c1 = d2 < a1, c2 = d2 < a2;
                a2 = c1 ? a1 : (c2 ? d2 : a2);  i2 = c1 ? i1 : (c2 ? idx : i2);
                a1 = c0 ? a0 : (c1 ? d2 : a1);  i1 = c0 ? i0 : (c1 ? idx : i1);
                a0 = c0 ? d2 : a0;              i0 = c0 ? idx : i0;
            }
        }
    }

    // margin = distance to nearest unsearched in-domain region
    float margin = 3.4e38f;
    if (bx >= 2)     margin = fminf(margin, qx - (bx - 1) * BINW);
    if (bx <= G - 3) margin = fminf(margin, (bx + 2) * BINW - qx);
    if (by >= 2)     margin = fminf(margin, qy - (by - 1) * BINW);
    if (by <= G - 3) margin = fminf(margin, (by + 2) * BINW - qy);
    if (bz >= 2)     margin = fminf(margin, qz - (bz - 1) * BINW);
    if (bz <= G - 3) margin = fminf(margin, (bz + 2) * BINW - qz);

    if (a2 > margin * margin) {
        // exact fallback: full batch scan (reset state first)
        a0 = a1 = a2 = 3.4e38f; i0 = i1 = i2 = 0;
        int s = batch * N2PB, e = s + N2PB;
#pragma unroll 1
        for (int j = s; j < e; j++) {
            float4 c = g_b2[j];
            float dx = qx - c.x, dy = qy - c.y, dz = qz - c.z;
            float d2 = fmaf(dx, dx, fmaf(dy, dy, dz * dz));
            int idx = __float_as_int(c.w);
            bool c0 = d2 < a0, c1 = d2 < a1, c2 = d2 < a2;
            a2 = c1 ? a1 : (c2 ? d2 : a2);  i2 = c1 ? i1 : (c2 ? idx : i2);
            a1 = c0 ? a0 : (c1 ? d2 : a1);  i1 = c0 ? i0 : (c1 ? idx : i1);
            a0 = c0 ? d2 : a0;              i0 = c0 ? idx : i0;
        }
    }

    g_kd[0][orig] = a0; g_ki[0][orig] = i0;
    g_kd[1][orig] = a1; g_ki[1][orig] = i1;
    g_kd[2][orig] = a2; g_ki[2][orig] = i2;
}

// ---------------------------------------------------------------------------
// Interp weights + gather + RMW into out (coalesced over queries).
// ---------------------------------------------------------------------------
__global__ void __launch_bounds__(256) interp_kernel(float* __restrict__ out)
{
    const int ng = blockIdx.x * 256 + threadIdx.x;
    const int batch = ng >> 14;

    float a0 = g_kd[0][ng], a1 = g_kd[1][ng], a2 = g_kd[2][ng];
    int   i0 = g_ki[0][ng], i1 = g_ki[1][ng], i2 = g_ki[2][ng];

    float w0 = 1.f / (a0 + 1e-8f);
    float w1 = 1.f / (a1 + 1e-8f);
    float w2 = 1.f / (a2 + 1e-8f);
    float inv = 1.f / (w0 + w1 + w2);
    w0 *= inv; w1 *= inv; w2 *= inv;

    const float4* f0 = (const float4*)(g_y2t + (size_t)(batch * N2PB + i0) * CV);
    const float4* f1 = (const float4*)(g_y2t + (size_t)(batch * N2PB + i1) * CV);
    const float4* f2 = (const float4*)(g_y2t + (size_t)(batch * N2PB + i2) * CV);
    float* op = out + ng;

#pragma unroll 4
    for (int c4 = 0; c4 < CV / 4; c4++) {
        float4 a = f0[c4], b = f1[c4], c = f2[c4];
        op[(size_t)(4 * c4 + 0) * N1TOT] += w0 * a.x + w1 * b.x + w2 * c.x;
        op[(size_t)(4 * c4 + 1) * N1TOT] += w0 * a.y + w1 * b.y + w2 * c.y;
        op[(size_t)(4 * c4 + 2) * N1TOT] += w0 * a.z + w1 * b.z + w2 * c.z;
        op[(size_t)(4 * c4 + 3) * N1TOT] += w0 * a.w + w1 * b.w + w2 * c.w;
    }
}

// ---------------------------------------------------------------------------
extern "C" void kernel_launch(void* const* d_in, const int* in_sizes, int n_in,
                              void* d_out, int out_size)
{
    const float* p1  = (const float*)d_in[0];
    const float* x1  = (const float*)d_in[1];
    const float* p2  = (const float*)d_in[3];
    const float* x2  = (const float*)d_in[4];
    const float* w1f = (const float*)d_in[6];
    const float* w1d = (const float*)d_in[7];
    const float* w2f = (const float*)d_in[8];
    const float* w2d = (const float*)d_in[9];
    float* out = (float*)d_out;

    const int SVN = (32 * WS2 + 32 * 3 * 32) * 8;   // 41472 B

    cudaFuncSetAttribute((const void*)vn_fused_kernel,
                         cudaFuncAttributeMaxDynamicSharedMemorySize, SVN);

    // VN layers: blocks [0,512): y2 -> g_y2t ; [512,2560): y1 -> out
    vn_fused_kernel<<<2560, 256, SVN>>>(x1, w1f, w1d, x2, w2f, w2d, out);

    // Spatial bin build (p1 and p2)
    zero_kernel<<<16, 256>>>();
    bin_count_kernel<<<(N2TOT + N1TOT) / 256, 256>>>(p1, p2);
    prefix_kernel<<<2, 256>>>();
    bin_scatter_kernel<<<(N2TOT + N1TOT) / 256, 256>>>(p1, p2);

    // 3-NN via bins (bin-sorted queries)
    knn_bin_kernel<<<N1TOT / 256, 256>>>();

    // interpolation + add into out
    interp_kernel<<<N1TOT / 256, 256>>>(out);
}